// round 3
// baseline (speedup 1.0000x reference)
#include <cuda_runtime.h>
#include <cuda_bf16.h>

#define N_NODES 131072
#define NG      4096        // graphs
#define NPG     32          // nodes per graph
#define NE      1048576     // edges per branch
#define SDIM    64
#define HDIM    128
#define CAP     64          // bucket capacity per (branch, graph)

// ---------------- scratch (device globals; no allocations allowed) ----------
__device__ int   g_cnt[2][NG];
__device__ int   g_bucket[2][NG][CAP];
__device__ float g_wsd[2][2][SDIM];   // [branch][{src,dst}][s] : folded W@att
__device__ int   g_is64[2];

// ---------------- K0: zero counters, detect edge dtype, fold W@att ----------
__global__ void k0_prep(const float* __restrict__ upW, const float* __restrict__ upAs,
                        const float* __restrict__ upAd,
                        const float* __restrict__ dnW, const float* __restrict__ dnAs,
                        const float* __restrict__ dnAd,
                        const int* __restrict__ upE, const int* __restrict__ dnE) {
    int tid = threadIdx.x;

    // zero per-graph counters
    for (int i = tid; i < 2 * NG; i += blockDim.x)
        ((int*)g_cnt)[i] = 0;

    // dtype detection: if edge_index is int64, the high 32-bit words of the
    // first 64 entries are all zero (indices < 2^31). If int32, those words
    // are random node indices (all-zero probability ~0).
    __shared__ int nz[2];
    if (tid < 2) nz[tid] = 0;
    __syncthreads();
    if (tid < 128) {
        int b = tid >> 6;
        int i = tid & 63;
        const int* p = b ? dnE : upE;
        if (p[2 * i + 1] != 0) atomicOr(&nz[b], 1);
    }
    __syncthreads();
    if (tid < 2) g_is64[tid] = (nz[tid] == 0) ? 1 : 0;

    // folded attention vectors: w[s] = sum_h W[s,h] * att[h]
    // 256 entries total: tid -> (branch, which, s)
    {
        int b = tid >> 7;
        int v = (tid >> 6) & 1;
        int s = tid & 63;
        const float* W = b ? dnW : upW;
        const float* a = b ? (v ? dnAd : dnAs) : (v ? upAd : upAs);
        float acc = 0.f;
        #pragma unroll 8
        for (int h = 0; h < HDIM; h++) acc += W[s * HDIM + h] * a[h];
        g_wsd[b][v][s] = acc;
    }
}

// ---------------- K1: filter edges with dst%32==31, bucket (g, src) ---------
__global__ void k1_filter(const int* __restrict__ upE, const int* __restrict__ dnE) {
    long long idx = (long long)blockIdx.x * blockDim.x + threadIdx.x;
    if (idx >= 2LL * NE) return;
    int b = (idx >= NE) ? 1 : 0;
    long long e = idx - (long long)b * NE;
    const int* p = b ? dnE : upE;
    int stride = g_is64[b] ? 2 : 1;          // read low word for int64
    int dst = p[(NE + e) * stride];
    if ((dst & 31) == 31) {
        int g = dst >> 5;
        int src = p[e * stride];
        int pos = atomicAdd(&g_cnt[b][g], 1);
        if (pos < CAP) g_bucket[b][g][pos] = src;
    }
}

// ---------------- K2: per-(graph,branch) softmax-aggregate + GEMV + fuse ----
__global__ __launch_bounds__(64) void k2_graph(
    const float* __restrict__ upx, const float* __restrict__ dnx,
    const float* __restrict__ upW, const float* __restrict__ dnW,
    const float* __restrict__ upB, const float* __restrict__ dnB,
    const float* __restrict__ mlpW, const float* __restrict__ mlpB,
    float* __restrict__ out) {

    int g = blockIdx.x;
    int b = threadIdx.x >> 5;   // warp 0 = up branch, warp 1 = down branch
    int l = threadIdx.x & 31;

    const float* x    = b ? dnx : upx;
    const float* W    = b ? dnW : upW;
    const float* bias = b ? dnB : upB;

    float ws0 = g_wsd[b][0][l], ws1 = g_wsd[b][0][l + 32];
    float wd0 = g_wsd[b][1][l], wd1 = g_wsd[b][1][l + 32];

    // a_dst for the terminal node of this graph
    int dnode = g * NPG + (NPG - 1);
    float xd0 = x[dnode * SDIM + l];
    float xd1 = x[dnode * SDIM + 32 + l];
    float part = xd0 * wd0 + xd1 * wd1;
    #pragma unroll
    for (int o = 16; o; o >>= 1) part += __shfl_xor_sync(0xffffffffu, part, o);
    float a_dst = part;

    int n = g_cnt[b][g];
    if (n > CAP) n = CAP;

    // un-shifted softmax accumulation (logits are O(10), exp is safe)
    float denom = 0.f, acc0 = 0.f, acc1 = 0.f;
    for (int i = 0; i < n; i++) {
        int src = g_bucket[b][g][i];
        float xv0 = x[src * SDIM + l];
        float xv1 = x[src * SDIM + 32 + l];
        float ps = xv0 * ws0 + xv1 * ws1;
        #pragma unroll
        for (int o = 16; o; o >>= 1) ps += __shfl_xor_sync(0xffffffffu, ps, o);
        float ev = ps + a_dst;
        ev = ev > 0.f ? ev : 0.2f * ev;        // leaky_relu(0.2)
        float pe = __expf(ev);
        denom += pe;
        acc0 += pe * xv0;
        acc1 += pe * xv1;
    }
    float inv = 1.f / (denom + 1e-16f);

    __shared__ float sh_xagg[2][SDIM];
    __shared__ float sh_sig[2][HDIM];
    sh_xagg[b][l]      = acc0 * inv;
    sh_xagg[b][l + 32] = acc1 * inv;
    __syncwarp();

    // h_out = xagg @ W  (64x128), 4 outputs per lane
    float ho0 = 0.f, ho1 = 0.f, ho2 = 0.f, ho3 = 0.f;
    #pragma unroll 8
    for (int s = 0; s < SDIM; s++) {
        float xa = sh_xagg[b][s];
        const float* Wr = W + s * HDIM;
        ho0 += xa * Wr[l];
        ho1 += xa * Wr[l + 32];
        ho2 += xa * Wr[l + 64];
        ho3 += xa * Wr[l + 96];
    }
    float hv[4] = {ho0, ho1, ho2, ho3};
    #pragma unroll
    for (int k = 0; k < 4; k++) {
        float v = hv[k] + bias[l + 32 * k];
        sh_sig[b][l + 32 * k] = 1.f / (1.f + __expf(-v));
    }
    __syncthreads();

    // fused epilogue: y[g] = sum_h sig_up*sig_dn*mlpW[h] + mlp_b
    if (b == 0) {
        float s = 0.f;
        #pragma unroll
        for (int k = 0; k < 4; k++) {
            int h = l + 32 * k;
            s += sh_sig[0][h] * sh_sig[1][h] * mlpW[h];
        }
        #pragma unroll
        for (int o = 16; o; o >>= 1) s += __shfl_xor_sync(0xffffffffu, s, o);
        if (l == 0) out[g] = s + mlpB[0];
    }
}

// ---------------- launch ----------------------------------------------------
extern "C" void kernel_launch(void* const* d_in, const int* in_sizes, int n_in,
                              void* d_out, int out_size) {
    const float* up_x  = (const float*)d_in[0];
    const int*   up_e  = (const int*)  d_in[1];
    const float* dn_x  = (const float*)d_in[3];
    const int*   dn_e  = (const int*)  d_in[4];
    const float* upW   = (const float*)d_in[6];
    const float* upAs  = (const float*)d_in[7];
    const float* upAd  = (const float*)d_in[8];
    const float* upB   = (const float*)d_in[9];
    const float* dnW   = (const float*)d_in[10];
    const float* dnAs  = (const float*)d_in[11];
    const float* dnAd  = (const float*)d_in[12];
    const float* dnB   = (const float*)d_in[13];
    const float* mlpW  = (const float*)d_in[14];
    const float* mlpB  = (const float*)d_in[15];
    float* out = (float*)d_out;

    k0_prep<<<1, 256>>>(upW, upAs, upAd, dnW, dnAs, dnAd, up_e, dn_e);
    k1_filter<<<(2 * NE) / 256, 256>>>(up_e, dn_e);
    k2_graph<<<NG, 64>>>(up_x, dn_x, upW, dnW, upB, dnB, mlpW, mlpB, out);
}

// round 6
// speedup vs baseline: 1.7400x; 1.7400x over previous
#include <cuda_runtime.h>
#include <cuda_bf16.h>

#define N_NODES 131072
#define NG      4096        // graphs
#define NPG     32          // nodes per graph
#define NE      1048576     // edges per branch
#define SDIM    64
#define HDIM    128
#define CAP     64          // bucket capacity per (branch, graph)

// ---------------- scratch (device globals; no allocations allowed) ----------
__device__ int   g_cnt[2][NG];
__device__ int   g_bucket[2][NG][CAP];
__device__ float g_wsd[2][2][SDIM];   // [branch][{src,dst}][s] : folded W@att

// ---------------- K0: zero counters + fold W@att (parallel) -----------------
// grid = 33 blocks x 256 threads.
//   block 32     : zero counters
//   blocks 0..31 : warp-per-dot fold (8 warps/block * 32 blocks = 256 dots)
__global__ void k0_prep(const float* __restrict__ upW, const float* __restrict__ upAs,
                        const float* __restrict__ upAd,
                        const float* __restrict__ dnW, const float* __restrict__ dnAs,
                        const float* __restrict__ dnAd) {
    int tid = threadIdx.x;

    if (blockIdx.x == 32) {
        // zero per-graph counters (8192 ints / 256 threads = 32 each)
        #pragma unroll
        for (int i = 0; i < 32; i++)
            ((int*)g_cnt)[tid + 256 * i] = 0;
        return;
    }

    // fold: one warp per output scalar w[b][v][s] = sum_h W[s,h]*att[h]
    int w  = blockIdx.x * 8 + (tid >> 5);   // global warp id, 0..255
    int l  = tid & 31;
    int b  = w >> 7;
    int v  = (w >> 6) & 1;
    int s  = w & 63;
    const float* W = b ? dnW : upW;
    const float* a = b ? (v ? dnAd : dnAs) : (v ? upAd : upAs);

    float4 wv = ((const float4*)(W + s * HDIM))[l];
    float4 av = ((const float4*)a)[l];
    float acc = wv.x * av.x + wv.y * av.y + wv.z * av.z + wv.w * av.w;
    #pragma unroll
    for (int o = 16; o; o >>= 1) acc += __shfl_xor_sync(0xffffffffu, acc, o);
    if (l == 0) g_wsd[b][v][s] = acc;
}

// ---------------- K1: filter edges with dst%32==31, bucket (g, src) ---------
// 4 edges per thread, vectorized dst reads. is64_* decided on host from sizes.
__global__ void k1_filter(const int* __restrict__ upE, const int* __restrict__ dnE,
                          int is64_up, int is64_dn) {
    long long t = (long long)blockIdx.x * blockDim.x + threadIdx.x;
    long long e4 = t * 4;                       // first edge of this thread's 4
    int b = (e4 >= NE) ? 1 : 0;
    long long e = e4 - (long long)b * NE;
    const int* p = b ? dnE : upE;
    int is64 = b ? is64_dn : is64_up;

    int d[4];
    if (is64) {
        // dst low words at p[2*(NE+e) + 2k]; 4 edges = 32B = two int4 loads
        const int4* q = (const int4*)(p + 2 * (NE + e));
        int4 a0 = q[0], a1 = q[1];
        d[0] = a0.x; d[1] = a0.z; d[2] = a1.x; d[3] = a1.z;
    } else {
        int4 a0 = *(const int4*)(p + NE + e);
        d[0] = a0.x; d[1] = a0.y; d[2] = a0.z; d[3] = a0.w;
    }

    int stride = is64 ? 2 : 1;
    #pragma unroll
    for (int k = 0; k < 4; k++) {
        if ((d[k] & 31) == 31) {
            int g = d[k] >> 5;
            int src = p[(e + k) * stride];
            int pos = atomicAdd(&g_cnt[b][g], 1);
            if (pos < CAP) g_bucket[b][g][pos] = src;
        }
    }
}

// ---------------- K2: per-(graph,branch) softmax-aggregate + GEMV + fuse ----
__global__ __launch_bounds__(64) void k2_graph(
    const float* __restrict__ upx, const float* __restrict__ dnx,
    const float* __restrict__ upW, const float* __restrict__ dnW,
    const float* __restrict__ upB, const float* __restrict__ dnB,
    const float* __restrict__ mlpW, const float* __restrict__ mlpB,
    float* __restrict__ out) {

    int g = blockIdx.x;
    int b = threadIdx.x >> 5;   // warp 0 = up branch, warp 1 = down branch
    int l = threadIdx.x & 31;

    const float* x    = b ? dnx : upx;
    const float* W    = b ? dnW : upW;
    const float* bias = b ? dnB : upB;

    __shared__ int   sh_src[2][CAP];
    __shared__ float sh_xagg[2][SDIM];
    __shared__ float sh_sig[2][HDIM];

    int n = g_cnt[b][g];
    if (n > CAP) n = CAP;
    // stage bucket list in shared (coalesced, then reread via LDS)
    if (l < CAP / 2) {
        ((int2*)sh_src[b])[l] = ((const int2*)g_bucket[b][g])[l];
    }
    __syncwarp();

    float ws0 = g_wsd[b][0][l], ws1 = g_wsd[b][0][l + 32];
    float wd0 = g_wsd[b][1][l], wd1 = g_wsd[b][1][l + 32];

    // a_dst for the terminal node of this graph
    int dnode = g * NPG + (NPG - 1);
    float xd0 = x[dnode * SDIM + l];
    float xd1 = x[dnode * SDIM + 32 + l];
    float part = xd0 * wd0 + xd1 * wd1;
    #pragma unroll
    for (int o = 16; o; o >>= 1) part += __shfl_xor_sync(0xffffffffu, part, o);
    float a_dst = part;

    // un-shifted softmax accumulation (logits are O(10), exp is safe in fp32)
    float denom = 0.f, acc0 = 0.f, acc1 = 0.f;
    for (int i = 0; i < n; i++) {
        int src = sh_src[b][i];
        float xv0 = x[src * SDIM + l];
        float xv1 = x[src * SDIM + 32 + l];
        float ps = xv0 * ws0 + xv1 * ws1;
        #pragma unroll
        for (int o = 16; o; o >>= 1) ps += __shfl_xor_sync(0xffffffffu, ps, o);
        float ev = ps + a_dst;
        ev = ev > 0.f ? ev : 0.2f * ev;        // leaky_relu(0.2)
        float pe = __expf(ev);
        denom += pe;
        acc0 += pe * xv0;
        acc1 += pe * xv1;
    }
    float inv = 1.f / (denom + 1e-16f);

    sh_xagg[b][l]      = acc0 * inv;
    sh_xagg[b][l + 32] = acc1 * inv;
    __syncwarp();

    // h_out = xagg @ W  (64x128), 4 outputs per lane
    float ho0 = 0.f, ho1 = 0.f, ho2 = 0.f, ho3 = 0.f;
    #pragma unroll 8
    for (int s = 0; s < SDIM; s++) {
        float xa = sh_xagg[b][s];
        const float* Wr = W + s * HDIM;
        ho0 += xa * Wr[l];
        ho1 += xa * Wr[l + 32];
        ho2 += xa * Wr[l + 64];
        ho3 += xa * Wr[l + 96];
    }
    float hv[4] = {ho0, ho1, ho2, ho3};
    #pragma unroll
    for (int k = 0; k < 4; k++) {
        float v = hv[k] + bias[l + 32 * k];
        sh_sig[b][l + 32 * k] = 1.f / (1.f + __expf(-v));
    }
    __syncthreads();

    // fused epilogue: y[g] = sum_h sig_up*sig_dn*mlpW[h] + mlp_b
    if (b == 0) {
        float s = 0.f;
        #pragma unroll
        for (int k = 0; k < 4; k++) {
            int h = l + 32 * k;
            s += sh_sig[0][h] * sh_sig[1][h] * mlpW[h];
        }
        #pragma unroll
        for (int o = 16; o; o >>= 1) s += __shfl_xor_sync(0xffffffffu, s, o);
        if (l == 0) out[g] = s + mlpB[0];
    }
}

// ---------------- launch ----------------------------------------------------
extern "C" void kernel_launch(void* const* d_in, const int* in_sizes, int n_in,
                              void* d_out, int out_size) {
    const float* up_x  = (const float*)d_in[0];
    const int*   up_e  = (const int*)  d_in[1];
    const float* dn_x  = (const float*)d_in[3];
    const int*   dn_e  = (const int*)  d_in[4];
    const float* upW   = (const float*)d_in[6];
    const float* upAs  = (const float*)d_in[7];
    const float* upAd  = (const float*)d_in[8];
    const float* upB   = (const float*)d_in[9];
    const float* dnW   = (const float*)d_in[10];
    const float* dnAs  = (const float*)d_in[11];
    const float* dnAd  = (const float*)d_in[12];
    const float* dnB   = (const float*)d_in[13];
    const float* mlpW  = (const float*)d_in[14];
    const float* mlpB  = (const float*)d_in[15];
    float* out = (float*)d_out;

    // int64 edge tensors arrive as int32 words with doubled element count:
    // 2*2*NE = 4*NE words vs 2*NE for true int32.
    int is64_up = (in_sizes[1] >= 4 * NE) ? 1 : 0;
    int is64_dn = (in_sizes[4] >= 4 * NE) ? 1 : 0;

    k0_prep<<<33, 256>>>(upW, upAs, upAd, dnW, dnAs, dnAd);
    k1_filter<<<(2 * NE) / (256 * 4), 256>>>(up_e, dn_e, is64_up, is64_dn);
    k2_graph<<<NG, 64>>>(up_x, dn_x, upW, dnW, upB, dnB, mlpW, mlpB, out);
}